// round 1
// baseline (speedup 1.0000x reference)
#include <cuda_runtime.h>
#include <cstdint>

#define HH 128
#define WW 192
#define CC_TOT 256
#define BB 8
#define TILE_W 32
#define TILE_H 16
#define HALO_W 40
#define HALO_H 24
#define CHUNK 8
#define NCHUNK (CC_TOT / CHUNK)
#define NTHREADS 128
#define PLANE ((size_t)HH * WW)

struct Smem {
    float prevS[2][CHUNK][HALO_H][HALO_W];   // 61440 B
    float currS[2][CHUNK][TILE_H][TILE_W];   // 32768 B
    float sspInv[HALO_H * HALO_W];           //  3840 B
};
#define SMEM_BYTES ((int)sizeof(Smem))

__device__ __forceinline__ void cp16(uint32_t dst, const float* src, int szbytes) {
    asm volatile("cp.async.cg.shared.global [%0], [%1], 16, %2;\n"
                 :: "r"(dst), "l"(src), "r"(szbytes) : "memory");
}

__global__ void __launch_bounds__(NTHREADS, 2)
corr_kernel(const float* __restrict__ curr, const float* __restrict__ prev,
            float* __restrict__ out)
{
    extern __shared__ char smraw[];
    Smem& sm = *reinterpret_cast<Smem*>(smraw);

    const int tid = threadIdx.x;
    const int tx  = tid & 7;          // 8 x-groups
    const int ty  = tid >> 3;         // 16 rows
    const int tx4 = tx * 4;
    const int x0  = blockIdx.x * TILE_W;
    const int y0  = blockIdx.y * TILE_H;
    const int bb  = blockIdx.z;

    const float* currB = curr + (size_t)bb * CC_TOT * PLANE;
    const float* prevB = prev + (size_t)bb * CC_TOT * PLANE;

    // ------- async staging of one 8-channel chunk -------
    auto issue_chunk = [&](int c0, int buf) {
        // prev halo: 24x40 x 8ch = 1920 float4 -> 15 per thread
        #pragma unroll
        for (int t = 0; t < 15; t++) {
            int fi  = tid + t * NTHREADS;          // < 1920
            int cc  = fi / 240;
            int r   = fi - cc * 240;
            int sy  = r / 10;
            int sx4 = r - sy * 10;
            int gy  = y0 - 4 + sy;
            int gx  = x0 - 4 + sx4 * 4;
            bool ok = ((unsigned)gy < HH) && ((unsigned)gx < WW);
            const float* src = prevB + ((size_t)(c0 + cc) * HH + (ok ? gy : 0)) * WW + (ok ? gx : 0);
            uint32_t dst = (uint32_t)__cvta_generic_to_shared(&sm.prevS[buf][cc][sy][sx4 * 4]);
            cp16(dst, src, ok ? 16 : 0);           // src-size 0 => zero fill (pad semantics)
        }
        // curr tile: 16x32 x 8ch = 1024 float4 -> 8 per thread (always in bounds)
        #pragma unroll
        for (int t = 0; t < 8; t++) {
            int fi  = tid + t * NTHREADS;          // < 1024
            int cc  = fi >> 7;
            int r   = fi & 127;
            int sy  = r >> 3;
            int sx4 = r & 7;
            const float* src = currB + ((size_t)(c0 + cc) * HH + (y0 + sy)) * WW + x0 + sx4 * 4;
            uint32_t dst = (uint32_t)__cvta_generic_to_shared(&sm.currS[buf][cc][sy][sx4 * 4]);
            cp16(dst, src, 16);
        }
        asm volatile("cp.async.commit_group;\n" ::: "memory");
    };

    // ------- accumulators -------
    float4 acc[33];
    #pragma unroll
    for (int o = 0; o < 33; o++) acc[o] = make_float4(0.f, 0.f, 0.f, 0.f);
    float4 ssqc = make_float4(0.f, 0.f, 0.f, 0.f);
    float4 sqpA = make_float4(0.f, 0.f, 0.f, 0.f);
    float4 sqpB = make_float4(0.f, 0.f, 0.f, 0.f);

    issue_chunk(0, 0);

    #pragma unroll 1
    for (int k = 0; k < NCHUNK; k++) {
        const int buf = k & 1;
        if (k < NCHUNK - 1) {
            issue_chunk((k + 1) * CHUNK, buf ^ 1);
            asm volatile("cp.async.wait_group 1;\n" ::: "memory");
        } else {
            asm volatile("cp.async.wait_group 0;\n" ::: "memory");
        }
        __syncthreads();

        const float (*pS)[HALO_H][HALO_W] = sm.prevS[buf];
        const float (*cS)[TILE_H][TILE_W] = sm.currS[buf];

        // prev sum-of-squares for halo pixels (fixed pixel-group per thread)
        {
            const float4* pf4 = reinterpret_cast<const float4*>(&pS[0][0][0]);
            #pragma unroll
            for (int cc = 0; cc < CHUNK; cc++) {
                float4 v = pf4[cc * 240 + tid];
                sqpA.x = fmaf(v.x, v.x, sqpA.x);
                sqpA.y = fmaf(v.y, v.y, sqpA.y);
                sqpA.z = fmaf(v.z, v.z, sqpA.z);
                sqpA.w = fmaf(v.w, v.w, sqpA.w);
                if (tid < 112) {
                    float4 w = pf4[cc * 240 + tid + 128];
                    sqpB.x = fmaf(w.x, w.x, sqpB.x);
                    sqpB.y = fmaf(w.y, w.y, sqpB.y);
                    sqpB.z = fmaf(w.z, w.z, sqpB.z);
                    sqpB.w = fmaf(w.w, w.w, sqpB.w);
                }
            }
        }

        // main correlation accumulation
        #pragma unroll
        for (int cc = 0; cc < CHUNK; cc++) {
            float4 cv = *reinterpret_cast<const float4*>(&cS[cc][ty][tx4]);
            ssqc.x = fmaf(cv.x, cv.x, ssqc.x);
            ssqc.y = fmaf(cv.y, cv.y, ssqc.y);
            ssqc.z = fmaf(cv.z, cv.z, ssqc.z);
            ssqc.w = fmaf(cv.w, cv.w, ssqc.w);

            float s[12];
#define LOADSEG_FULL(PY) do { \
    const float4* _p = reinterpret_cast<const float4*>(&pS[cc][(PY)][tx4]); \
    float4 _a = _p[0], _b2 = _p[1], _c2 = _p[2]; \
    s[0]=_a.x; s[1]=_a.y; s[2]=_a.z; s[3]=_a.w; \
    s[4]=_b2.x; s[5]=_b2.y; s[6]=_b2.z; s[7]=_b2.w; \
    s[8]=_c2.x; s[9]=_c2.y; s[10]=_c2.z; s[11]=_c2.w; } while (0)
#define LOADSEG_MID(PY) do { \
    const float* _r = &pS[cc][(PY)][tx4]; \
    float2 _a = *reinterpret_cast<const float2*>(_r + 2); \
    float4 _b2 = *reinterpret_cast<const float4*>(_r + 4); \
    float2 _c2 = *reinterpret_cast<const float2*>(_r + 8); \
    s[2]=_a.x; s[3]=_a.y; s[4]=_b2.x; s[5]=_b2.y; s[6]=_b2.z; s[7]=_b2.w; \
    s[8]=_c2.x; s[9]=_c2.y; } while (0)
#define CFMA(o, dx) do { \
    acc[o].x = fmaf(cv.x, s[4 + (dx)], acc[o].x); \
    acc[o].y = fmaf(cv.y, s[5 + (dx)], acc[o].y); \
    acc[o].z = fmaf(cv.z, s[6 + (dx)], acc[o].z); \
    acc[o].w = fmaf(cv.w, s[7 + (dx)], acc[o].w); } while (0)

            LOADSEG_FULL(ty + 0); CFMA(0,-4);  CFMA(1,-2);  CFMA(2,0);   CFMA(3,2);   CFMA(4,4);
            LOADSEG_FULL(ty + 2); CFMA(5,-4);  CFMA(6,-2);  CFMA(7,0);   CFMA(8,2);   CFMA(9,4);
            LOADSEG_MID (ty + 3); CFMA(10,-1); CFMA(11,0);  CFMA(12,1);
            LOADSEG_FULL(ty + 4); CFMA(13,-4); CFMA(14,-2); CFMA(15,-1); CFMA(16,0);
                                  CFMA(17,1);  CFMA(18,2);  CFMA(19,4);
            LOADSEG_MID (ty + 5); CFMA(20,-1); CFMA(21,0);  CFMA(22,1);
            LOADSEG_FULL(ty + 6); CFMA(23,-4); CFMA(24,-2); CFMA(25,0);  CFMA(26,2);  CFMA(27,4);
            LOADSEG_FULL(ty + 8); CFMA(28,-4); CFMA(29,-2); CFMA(30,0);  CFMA(31,2);  CFMA(32,4);
        }
        __syncthreads();
    }

    // ------- epilogue: inverse norms + scale + store -------
    {
        int j = tid * 4;
        sm.sspInv[j + 0] = sqpA.x > 0.f ? rsqrtf(sqpA.x) : 0.f;
        sm.sspInv[j + 1] = sqpA.y > 0.f ? rsqrtf(sqpA.y) : 0.f;
        sm.sspInv[j + 2] = sqpA.z > 0.f ? rsqrtf(sqpA.z) : 0.f;
        sm.sspInv[j + 3] = sqpA.w > 0.f ? rsqrtf(sqpA.w) : 0.f;
        if (tid < 112) {
            int j2 = (tid + 128) * 4;
            sm.sspInv[j2 + 0] = sqpB.x > 0.f ? rsqrtf(sqpB.x) : 0.f;
            sm.sspInv[j2 + 1] = sqpB.y > 0.f ? rsqrtf(sqpB.y) : 0.f;
            sm.sspInv[j2 + 2] = sqpB.z > 0.f ? rsqrtf(sqpB.z) : 0.f;
            sm.sspInv[j2 + 3] = sqpB.w > 0.f ? rsqrtf(sqpB.w) : 0.f;
        }
    }
    __syncthreads();

    float4 invc;
    invc.x = rsqrtf(ssqc.x);
    invc.y = rsqrtf(ssqc.y);
    invc.z = rsqrtf(ssqc.z);
    invc.w = rsqrtf(ssqc.w);

    const int gy = y0 + ty;
    const int gx = x0 + tx4;
    float* outBase = out + (((size_t)bb * 33) * HH + gy) * WW + gx;

    {
        float s[12];
#define ESEG_FULL(PY) do { \
    const float4* _p = reinterpret_cast<const float4*>(&sm.sspInv[(PY) * HALO_W + tx4]); \
    float4 _a = _p[0], _b2 = _p[1], _c2 = _p[2]; \
    s[0]=_a.x; s[1]=_a.y; s[2]=_a.z; s[3]=_a.w; \
    s[4]=_b2.x; s[5]=_b2.y; s[6]=_b2.z; s[7]=_b2.w; \
    s[8]=_c2.x; s[9]=_c2.y; s[10]=_c2.z; s[11]=_c2.w; } while (0)
#define EPIST(o, dx) do { \
    float4 r; \
    r.x = acc[o].x * invc.x * s[4 + (dx)]; \
    r.y = acc[o].y * invc.y * s[5 + (dx)]; \
    r.z = acc[o].z * invc.z * s[6 + (dx)]; \
    r.w = acc[o].w * invc.w * s[7 + (dx)]; \
    *reinterpret_cast<float4*>(outBase + (size_t)(o) * PLANE) = r; } while (0)

        ESEG_FULL(ty + 0); EPIST(0,-4);  EPIST(1,-2);  EPIST(2,0);   EPIST(3,2);   EPIST(4,4);
        ESEG_FULL(ty + 2); EPIST(5,-4);  EPIST(6,-2);  EPIST(7,0);   EPIST(8,2);   EPIST(9,4);
        ESEG_FULL(ty + 3); EPIST(10,-1); EPIST(11,0);  EPIST(12,1);
        ESEG_FULL(ty + 4); EPIST(13,-4); EPIST(14,-2); EPIST(15,-1); EPIST(16,0);
                           EPIST(17,1);  EPIST(18,2);  EPIST(19,4);
        ESEG_FULL(ty + 5); EPIST(20,-1); EPIST(21,0);  EPIST(22,1);
        ESEG_FULL(ty + 6); EPIST(23,-4); EPIST(24,-2); EPIST(25,0);  EPIST(26,2);  EPIST(27,4);
        ESEG_FULL(ty + 8); EPIST(28,-4); EPIST(29,-2); EPIST(30,0);  EPIST(31,2);  EPIST(32,4);
    }
}

extern "C" void kernel_launch(void* const* d_in, const int* in_sizes, int n_in,
                              void* d_out, int out_size)
{
    const float* curr = (const float*)d_in[0];
    const float* prev = (const float*)d_in[1];
    float* out = (float*)d_out;

    cudaFuncSetAttribute(corr_kernel, cudaFuncAttributeMaxDynamicSharedMemorySize, SMEM_BYTES);

    dim3 grid(WW / TILE_W, HH / TILE_H, BB);   // 6 x 8 x 8 = 384 blocks
    corr_kernel<<<grid, NTHREADS, SMEM_BYTES>>>(curr, prev, out);
}

// round 2
// speedup vs baseline: 1.1142x; 1.1142x over previous
#include <cuda_runtime.h>
#include <cstdint>

#define HH 128
#define WW 192
#define CC_TOT 256
#define BB 8
#define TILE_W 32
#define TILE_H 16
#define HALO_W 40
#define HALO_H 24
#define CHUNK 4
#define NCHUNK (CC_TOT / CHUNK)
#define NT 128
#define PLANE ((size_t)HH * WW)

#define PREV_BUF_BYTES (CHUNK * HALO_H * HALO_W * 4)   // 15360
#define CURR_BUF_BYTES (CHUNK * TILE_H * TILE_W * 4)   // 8192
#define SM_PREV 0
#define SM_CURR (2 * PREV_BUF_BYTES)                   // 30720
#define SM_SSP  (SM_CURR + 2 * CURR_BUF_BYTES)         // 47104
#define SMEM_BYTES (SM_SSP + HALO_H * HALO_W * 4)      // 50944

typedef unsigned long long u64;

__device__ __forceinline__ void F2(u64 &d, u64 a, u64 b) {
    asm("fma.rn.f32x2 %0, %1, %2, %0;" : "+l"(d) : "l"(a), "l"(b));
}
__device__ __forceinline__ u64 M2(u64 a, u64 b) {
    u64 d; asm("mul.rn.f32x2 %0, %1, %2;" : "=l"(d) : "l"(a), "l"(b)); return d;
}
__device__ __forceinline__ u64 PK(unsigned a, unsigned b) {
    u64 d; asm("mov.b64 %0, {%1, %2};" : "=l"(d) : "r"(a), "r"(b)); return d;
}
__device__ __forceinline__ unsigned LOW(u64 a) {
    unsigned l, h; asm("mov.b64 {%0, %1}, %2;" : "=r"(l), "=r"(h) : "l"(a)); return l;
}
__device__ __forceinline__ unsigned HIW(u64 a) {
    unsigned l, h; asm("mov.b64 {%0, %1}, %2;" : "=r"(l), "=r"(h) : "l"(a)); return h;
}
__device__ __forceinline__ void cp16(uint32_t dst, const void* src, int szbytes) {
    asm volatile("cp.async.cg.shared.global [%0], [%1], 16, %2;\n"
                 :: "r"(dst), "l"(src), "r"(szbytes) : "memory");
}

__global__ void __launch_bounds__(NT, 3)
corr_kernel(const float* __restrict__ curr, const float* __restrict__ prev,
            float* __restrict__ out)
{
    extern __shared__ char smem[];

    const int tid = threadIdx.x;
    const int tx4 = (tid & 7) * 4;
    const int ty  = tid >> 3;
    const int x0  = blockIdx.x * TILE_W;
    const int y0  = blockIdx.y * TILE_H;
    const int bb  = blockIdx.z;

    const char* currB = (const char*)(curr + (size_t)bb * CC_TOT * PLANE);
    const char* prevB = (const char*)(prev + (size_t)bb * CC_TOT * PLANE);

    const uint32_t smA   = (uint32_t)__cvta_generic_to_shared(smem);
    const uint32_t smPrevA = smA + SM_PREV;
    const uint32_t smCurrA = smA + SM_CURR;

    // ---- staging precompute (per-thread fixed slots) ----
    // prev slot0 = tid, slot1 = tid+128 (valid if tid<112); 240 float4 per cc, 10 per row
    const int sy0 = tid / 10,         sx0 = tid - sy0 * 10;
    const int sy1 = (tid + 128) / 10, sx1 = (tid + 128) - sy1 * 10;
    const int gy0 = y0 - 4 + sy0, gx0 = x0 - 4 + sx0 * 4;
    const int gy1 = y0 - 4 + sy1, gx1 = x0 - 4 + sx1 * 4;
    const bool ok0 = ((unsigned)gy0 < HH) && ((unsigned)gx0 < WW);
    const bool ok1 = ((unsigned)gy1 < HH) && ((unsigned)gx1 < WW);
    const int pixOff0 = ok0 ? (gy0 * WW + gx0) * 4 : 0;
    const int pixOff1 = ok1 ? (gy1 * WW + gx1) * 4 : 0;
    const int sz0 = ok0 ? 16 : 0;
    const int sz1 = ok1 ? 16 : 0;
    const int cpixOff = ((y0 + ty) * WW + x0 + tx4) * 4;   // curr slot = tid

    // ---- accumulators (packed f32x2) ----
    u64 accL[33], accH[33];
    #pragma unroll
    for (int o = 0; o < 33; o++) { accL[o] = 0ull; accH[o] = 0ull; }
    u64 ssqL = 0ull, ssqH = 0ull;                 // curr sum-of-squares (4 pixels)
    u64 sq0L = 0ull, sq0H = 0ull;                 // prev sq, slot0
    u64 sq1L = 0ull, sq1H = 0ull;                 // prev sq, slot1

    // ---- stage chunk 0 ----
    {
        #pragma unroll
        for (int cc = 0; cc < CHUNK; cc++) {
            const size_t so = (size_t)cc * PLANE * 4;
            cp16(smPrevA + cc * 3840 + tid * 16, prevB + so + pixOff0, sz0);
            if (tid < 112)
                cp16(smPrevA + cc * 3840 + (tid + 128) * 16, prevB + so + pixOff1, sz1);
            cp16(smCurrA + cc * 2048 + tid * 16, currB + so + cpixOff, 16);
        }
        asm volatile("cp.async.commit_group;\n" ::: "memory");
    }

    const int rowOff = (ty * HALO_W + tx4) * 4;   // within-cc offset of segment base
    const int cvOff  = (ty * TILE_W + tx4) * 4;

    #pragma unroll 1
    for (int k = 0; k < NCHUNK; k++) {
        const int buf = k & 1;
        if (k < NCHUNK - 1) {
            const char* srcP = prevB + (size_t)(k + 1) * CHUNK * PLANE * 4;
            const char* srcC = currB + (size_t)(k + 1) * CHUNK * PLANE * 4;
            const uint32_t dP = smPrevA + (buf ^ 1) * PREV_BUF_BYTES;
            const uint32_t dC = smCurrA + (buf ^ 1) * CURR_BUF_BYTES;
            #pragma unroll
            for (int cc = 0; cc < CHUNK; cc++) {
                const size_t so = (size_t)cc * PLANE * 4;
                cp16(dP + cc * 3840 + tid * 16, srcP + so + pixOff0, sz0);
                if (tid < 112)
                    cp16(dP + cc * 3840 + (tid + 128) * 16, srcP + so + pixOff1, sz1);
                cp16(dC + cc * 2048 + tid * 16, srcC + so + cpixOff, 16);
            }
            asm volatile("cp.async.commit_group;\n" ::: "memory");
            asm volatile("cp.async.wait_group 1;\n" ::: "memory");
        } else {
            asm volatile("cp.async.wait_group 0;\n" ::: "memory");
        }
        __syncthreads();

        const char* pBuf = smem + SM_PREV + buf * PREV_BUF_BYTES;
        const char* cBuf = smem + SM_CURR + buf * CURR_BUF_BYTES;

        // prev sum-of-squares (fixed f4 slots per thread)
        #pragma unroll
        for (int cc = 0; cc < CHUNK; cc++) {
            const ulonglong2 v = *(const ulonglong2*)(pBuf + cc * 3840 + tid * 16);
            F2(sq0L, v.x, v.x); F2(sq0H, v.y, v.y);
            if (tid < 112) {
                const ulonglong2 w = *(const ulonglong2*)(pBuf + cc * 3840 + tid * 16 + 2048);
                F2(sq1L, w.x, w.x); F2(sq1H, w.y, w.y);
            }
        }

        // main correlation accumulation
        #pragma unroll
        for (int cc = 0; cc < CHUNK; cc++) {
            const ulonglong2 CV = *(const ulonglong2*)(cBuf + cc * 2048 + cvOff);
            const u64 cvL = CV.x, cvH = CV.y;
            F2(ssqL, cvL, cvL); F2(ssqH, cvH, cvH);

            const char* rowB = pBuf + cc * 3840 + rowOff;

#define ROW_FULL(R, O0) do { \
    const ulonglong2* _p = (const ulonglong2*)(rowB + (R) * (HALO_W * 4)); \
    const ulonglong2 q0 = _p[0], q1 = _p[1], q2 = _p[2]; \
    F2(accL[O0 + 0], cvL, q0.x); F2(accH[O0 + 0], cvH, q0.y); \
    F2(accL[O0 + 1], cvL, q0.y); F2(accH[O0 + 1], cvH, q1.x); \
    F2(accL[O0 + 2], cvL, q1.x); F2(accH[O0 + 2], cvH, q1.y); \
    F2(accL[O0 + 3], cvL, q1.y); F2(accH[O0 + 3], cvH, q2.x); \
    F2(accL[O0 + 4], cvL, q2.x); F2(accH[O0 + 4], cvH, q2.y); } while (0)

#define ROW_MID(R, M0) do { \
    const char* _rp = rowB + (R) * (HALO_W * 4); \
    const u64 a1 = *(const u64*)(_rp + 8); \
    const ulonglong2 q1 = *(const ulonglong2*)(_rp + 16); \
    const u64 a4 = *(const u64*)(_rp + 32); \
    const u64 P34 = PK(HIW(a1), LOW(q1.x)); \
    const u64 P56 = PK(HIW(q1.x), LOW(q1.y)); \
    const u64 P78 = PK(HIW(q1.y), LOW(a4)); \
    F2(accL[M0 + 0], cvL, P34);  F2(accH[M0 + 0], cvH, P56); \
    F2(accL[M0 + 1], cvL, q1.x); F2(accH[M0 + 1], cvH, q1.y); \
    F2(accL[M0 + 2], cvL, P56);  F2(accH[M0 + 2], cvH, P78); } while (0)

            ROW_FULL(0, 0);     // dy = -4
            ROW_FULL(2, 5);     // dy = -2
            ROW_MID (3, 10);    // dy = -1
            {                   // dy = 0: dx = -4,-2,-1,0,1,2,4 -> o13..o19
                const ulonglong2* _p = (const ulonglong2*)(rowB + 4 * (HALO_W * 4));
                const ulonglong2 q0 = _p[0], q1 = _p[1], q2 = _p[2];
                F2(accL[13], cvL, q0.x); F2(accH[13], cvH, q0.y);
                F2(accL[14], cvL, q0.y); F2(accH[14], cvH, q1.x);
                F2(accL[16], cvL, q1.x); F2(accH[16], cvH, q1.y);
                F2(accL[18], cvL, q1.y); F2(accH[18], cvH, q2.x);
                F2(accL[19], cvL, q2.x); F2(accH[19], cvH, q2.y);
                const u64 P34 = PK(HIW(q0.y), LOW(q1.x));
                const u64 P56 = PK(HIW(q1.x), LOW(q1.y));
                const u64 P78 = PK(HIW(q1.y), LOW(q2.x));
                F2(accL[15], cvL, P34); F2(accH[15], cvH, P56);
                F2(accL[17], cvL, P56); F2(accH[17], cvH, P78);
            }
            ROW_MID (5, 20);    // dy = 1
            ROW_FULL(6, 23);    // dy = 2
            ROW_FULL(8, 28);    // dy = 4
        }
        __syncthreads();
    }

    // ---- epilogue: inverse norms ----
    {
        float* ssp = (float*)(smem + SM_SSP);
        float4 r0;
        const float a = __uint_as_float(LOW(sq0L)), b = __uint_as_float(HIW(sq0L));
        const float c = __uint_as_float(LOW(sq0H)), d = __uint_as_float(HIW(sq0H));
        r0.x = a > 0.f ? rsqrtf(a) : 0.f;
        r0.y = b > 0.f ? rsqrtf(b) : 0.f;
        r0.z = c > 0.f ? rsqrtf(c) : 0.f;
        r0.w = d > 0.f ? rsqrtf(d) : 0.f;
        ((float4*)ssp)[tid] = r0;
        if (tid < 112) {
            float4 r1;
            const float e = __uint_as_float(LOW(sq1L)), f = __uint_as_float(HIW(sq1L));
            const float g = __uint_as_float(LOW(sq1H)), h = __uint_as_float(HIW(sq1H));
            r1.x = e > 0.f ? rsqrtf(e) : 0.f;
            r1.y = f > 0.f ? rsqrtf(f) : 0.f;
            r1.z = g > 0.f ? rsqrtf(g) : 0.f;
            r1.w = h > 0.f ? rsqrtf(h) : 0.f;
            ((float4*)ssp)[tid + 128] = r1;
        }
    }
    __syncthreads();

    u64 invL, invH;
    {
        const float i0 = rsqrtf(__uint_as_float(LOW(ssqL)));
        const float i1 = rsqrtf(__uint_as_float(HIW(ssqL)));
        const float i2 = rsqrtf(__uint_as_float(LOW(ssqH)));
        const float i3 = rsqrtf(__uint_as_float(HIW(ssqH)));
        invL = PK(__float_as_uint(i0), __float_as_uint(i1));
        invH = PK(__float_as_uint(i2), __float_as_uint(i3));
    }

    const char* srow = smem + SM_SSP + rowOff;
    char* outPix = (char*)(out + ((size_t)bb * 33 * HH + (y0 + ty)) * WW + x0 + tx4);

#define EST(O, BL, BH) do { \
    ulonglong2 _r; \
    _r.x = M2(M2(accL[O], invL), (BL)); \
    _r.y = M2(M2(accH[O], invH), (BH)); \
    *(ulonglong2*)(outPix + (size_t)(O) * (PLANE * 4)) = _r; } while (0)

#define EROW_FULL(R, O0) do { \
    const ulonglong2* _p = (const ulonglong2*)(srow + (R) * (HALO_W * 4)); \
    const ulonglong2 q0 = _p[0], q1 = _p[1], q2 = _p[2]; \
    EST(O0 + 0, q0.x, q0.y); \
    EST(O0 + 1, q0.y, q1.x); \
    EST(O0 + 2, q1.x, q1.y); \
    EST(O0 + 3, q1.y, q2.x); \
    EST(O0 + 4, q2.x, q2.y); } while (0)

#define EROW_MID(R, M0) do { \
    const char* _rp = srow + (R) * (HALO_W * 4); \
    const u64 a1 = *(const u64*)(_rp + 8); \
    const ulonglong2 q1 = *(const ulonglong2*)(_rp + 16); \
    const u64 a4 = *(const u64*)(_rp + 32); \
    const u64 P34 = PK(HIW(a1), LOW(q1.x)); \
    const u64 P56 = PK(HIW(q1.x), LOW(q1.y)); \
    const u64 P78 = PK(HIW(q1.y), LOW(a4)); \
    EST(M0 + 0, P34, P56); \
    EST(M0 + 1, q1.x, q1.y); \
    EST(M0 + 2, P56, P78); } while (0)

    EROW_FULL(0, 0);
    EROW_FULL(2, 5);
    EROW_MID (3, 10);
    {
        const ulonglong2* _p = (const ulonglong2*)(srow + 4 * (HALO_W * 4));
        const ulonglong2 q0 = _p[0], q1 = _p[1], q2 = _p[2];
        EST(13, q0.x, q0.y);
        EST(14, q0.y, q1.x);
        EST(16, q1.x, q1.y);
        EST(18, q1.y, q2.x);
        EST(19, q2.x, q2.y);
        const u64 P34 = PK(HIW(q0.y), LOW(q1.x));
        const u64 P56 = PK(HIW(q1.x), LOW(q1.y));
        const u64 P78 = PK(HIW(q1.y), LOW(q2.x));
        EST(15, P34, P56);
        EST(17, P56, P78);
    }
    EROW_MID (5, 20);
    EROW_FULL(6, 23);
    EROW_FULL(8, 28);
}

extern "C" void kernel_launch(void* const* d_in, const int* in_sizes, int n_in,
                              void* d_out, int out_size)
{
    const float* curr = (const float*)d_in[0];
    const float* prev = (const float*)d_in[1];
    float* out = (float*)d_out;

    cudaFuncSetAttribute(corr_kernel, cudaFuncAttributeMaxDynamicSharedMemorySize, SMEM_BYTES);

    dim3 grid(WW / TILE_W, HH / TILE_H, BB);   // 6 x 8 x 8 = 384 blocks
    corr_kernel<<<grid, NT, SMEM_BYTES>>>(curr, prev, out);
}